// round 16
// baseline (speedup 1.0000x reference)
#include <cuda_runtime.h>
#include <cuda_bf16.h>
#include <cstdint>

#define BATCH   4096
#define DM      1024
#define DS      16384
#define K_SEL   131072
#define H_TOTAL 67108864
#define WCAP    (2*1024*1024)
#define BCAP    8192
#define NOISE   1.5e-4f
#define MARGIN  0.04f
#define CAND_T  4.1f
#define ROWCAP  96
#define BLK_CAP 1024
#define NGRP    512
#define GCAP    1024
#define FHBINS  4096

// GEMM tiling: 3-stage cp.async pipeline, CTA 128x128, warp 64x32 (proven)
#define BM 128
#define BN 128
#define BK 64
#define STG_SZ   16384
#define OFF_A    0
#define OFF_B    49152
#define OFF_BIAS 98304
#define OFF_CV   98816
#define OFF_CI   102912
#define OFF_CNT  107008
#define OFF_BSE  107012
#define SMEM_GEMM 107264

#define SWZ(b) ((b) ^ (((b) >> 3) & 0x70))

// ------------------------- device scratch ------------------------------------
__device__ float          g_fx_fallback[H_TOTAL];
__device__ __nv_bfloat16  g_xb[BATCH * DM];
__device__ __nv_bfloat16  g_wbT[DS * DM];        // [n][k] bf16
__device__ float          g_wide_val[WCAP];
__device__ int            g_wide_idx[WCAP];
__device__ unsigned int   g_nwide;
__device__ unsigned int   g_fh1[FHBINS];         // fine hist of bf |h| (windowed u>>10)
__device__ unsigned int   g_fh2[FHBINS];         // fine hist of exact |h|
__device__ unsigned int   g_grp_cnt[NGRP];
__device__ int            g_bk_idx[NGRP * GCAP];
__device__ float          g_exact_val[NGRP * GCAP];
__device__ unsigned int   g_c_in, g_b_cnt;
__device__ int            g_b_idx[BCAP];
__device__ float          g_b_f32[BCAP];
__device__ double         g_b_v64[BCAP];
__device__ unsigned int   g_acc_cnt;             // accepted boundary list
__device__ int            g_acc_idx[BCAP];
__device__ float          g_acc_val[BCAP];
__device__ unsigned int   g_row_cnt[BATCH];
__device__ int            g_row_col[BATCH * ROWCAP];
__device__ float          g_row_val[BATCH * ROWCAP];

// ------------------------- PTX helpers ---------------------------------------
__device__ __forceinline__ uint32_t smem_u32(const void* p) {
    uint32_t a;
    asm("{ .reg .u64 t; cvta.to.shared.u64 t, %1; cvt.u32.u64 %0, t; }" : "=r"(a) : "l"(p));
    return a;
}
__device__ __forceinline__ void cpasync16(uint32_t dst, const void* src) {
    asm volatile("cp.async.cg.shared.global [%0], [%1], 16;" :: "r"(dst), "l"(src) : "memory");
}
__device__ __forceinline__ void cp_commit() { asm volatile("cp.async.commit_group;" ::: "memory"); }
__device__ __forceinline__ void cp_wait1()  { asm volatile("cp.async.wait_group 1;" ::: "memory"); }
__device__ __forceinline__ void cp_wait0()  { asm volatile("cp.async.wait_group 0;" ::: "memory"); }

__device__ __forceinline__ void ldsm_x4(uint32_t& r0, uint32_t& r1, uint32_t& r2, uint32_t& r3,
                                        uint32_t addr) {
    asm volatile("ldmatrix.sync.aligned.m8n8.x4.shared.b16 {%0,%1,%2,%3}, [%4];"
                 : "=r"(r0), "=r"(r1), "=r"(r2), "=r"(r3) : "r"(addr));
}
__device__ __forceinline__ void mma16816(float* d, const uint32_t* a, const uint32_t* b) {
    asm volatile(
        "mma.sync.aligned.m16n8k16.row.col.f32.bf16.bf16.f32 "
        "{%0,%1,%2,%3}, {%4,%5,%6,%7}, {%8,%9}, {%0,%1,%2,%3};"
        : "+f"(d[0]), "+f"(d[1]), "+f"(d[2]), "+f"(d[3])
        : "r"(a[0]), "r"(a[1]), "r"(a[2]), "r"(a[3]), "r"(b[0]), "r"(b[1]));
}

__device__ __forceinline__ unsigned fh_base() {
    return __float_as_uint(CAND_T) >> 10;
}
__device__ __forceinline__ int fh_key(float a) {
    int k = (int)(__float_as_uint(a) >> 10) - (int)fh_base();
    return max(0, min(FHBINS - 1, k));
}

// ------------------------- in-block k-th selection over a 4096-bin fine hist --
// Returns the >>10-granular bin (descending rank-K). All blocks agree.
__device__ __forceinline__ unsigned find_kth_fine(const unsigned* __restrict__ hist,
                                                  unsigned K, unsigned* sm /*>=257*/) {
    const int t = threadIdx.x;            // blockDim.x == 256
    unsigned vals[16], s = 0;
#pragma unroll
    for (int j = 0; j < 16; j++) { vals[j] = hist[FHBINS - 1 - (t * 16 + j)]; s += vals[j]; }
    sm[t] = s;
    __syncthreads();
    for (int off = 1; off < 256; off <<= 1) {
        unsigned v = (t >= off) ? sm[t - off] : 0;
        __syncthreads();
        sm[t] += v;
        __syncthreads();
    }
    const unsigned base = t ? sm[t - 1] : 0;
    if (base < K && sm[t] >= K) {
        unsigned cum = base;
#pragma unroll
        for (int j = 0; j < 16; j++) {
            cum += vals[j];
            if (cum >= K) { sm[256] = FHBINS - 1 - (t * 16 + j); break; }
        }
    }
    __syncthreads();
    const unsigned r = sm[256];
    __syncthreads();
    return r;
}

// ------------------------- reset ---------------------------------------------
__global__ void k_reset() {
    int i = blockIdx.x * blockDim.x + threadIdx.x;
    if (i < FHBINS) { g_fh1[i] = 0; g_fh2[i] = 0; }
    if (i < NGRP) g_grp_cnt[i] = 0;
    if (i < BATCH) g_row_cnt[i] = 0;
    if (i == 0) { g_nwide = 0; g_c_in = 0; g_b_cnt = 0; g_acc_cnt = 0; }
}

// ------------------------- converts ------------------------------------------
__global__ void k_cvt_x(const float* __restrict__ x) {
    const int n2 = BATCH * DM / 2;
    const int stride = gridDim.x * blockDim.x;
    __nv_bfloat162* o = (__nv_bfloat162*)g_xb;
    const float2* s = (const float2*)x;
    for (int i = blockIdx.x * blockDim.x + threadIdx.x; i < n2; i += stride)
        o[i] = __float22bfloat162_rn(s[i]);
}
// converts W_enc[k][n] -> g_wbT[n][k] for n in [n_lo, n_lo + 32*gridDim.x)
__global__ void k_cvt_wT(const float* __restrict__ W, int n_lo) {
    __shared__ float t[32][33];
    const int n0 = n_lo + blockIdx.x * 32, k0 = blockIdx.y * 32;
    const int tx = threadIdx.x, ty = threadIdx.y;  // 32 x 8
#pragma unroll
    for (int i = 0; i < 4; i++)
        t[ty + 8 * i][tx] = W[(size_t)(k0 + ty + 8 * i) * DS + n0 + tx];
    __syncthreads();
#pragma unroll
    for (int i = 0; i < 4; i++)
        g_wbT[(size_t)(n0 + ty + 8 * i) * DM + k0 + tx] = __float2bfloat16(t[tx][ty + 8 * i]);
}

// ------------------------- bf16 mma.sync GEMM, 3-stage pipeline --------------
__device__ __forceinline__ void load_tiles(uint32_t sb, int m0, int n0, int kt, int s, int tid) {
    const uint32_t ab = sb + OFF_A + s * STG_SZ;
#pragma unroll
    for (int i = 0; i < 4; i++) {
        int c = tid + i * 256;
        int row = c >> 3, chunk = c & 7;
        cpasync16(ab + SWZ((uint32_t)row * 128u + (uint32_t)chunk * 16u),
                  g_xb + (size_t)(m0 + row) * DM + kt * BK + chunk * 8);
    }
    const uint32_t bb = sb + OFF_B + s * STG_SZ;
#pragma unroll
    for (int i = 0; i < 4; i++) {
        int c = tid + i * 256;
        int row = c >> 3, chunk = c & 7;
        cpasync16(bb + SWZ((uint32_t)row * 128u + (uint32_t)chunk * 16u),
                  g_wbT + (size_t)(n0 + row) * DM + kt * BK + chunk * 8);
    }
    cp_commit();
}

__global__ __launch_bounds__(256, 2)
void k_gemm_bf(const float* __restrict__ bias) {
    extern __shared__ char smem[];
    const uint32_t sb = smem_u32(smem);
    const int tid = threadIdx.x, wid = tid >> 5, lane = tid & 31;
    const int m0 = blockIdx.y * BM, n0 = blockIdx.x * BN;
    const int wm = (wid & 1) * 64;
    const int wn = (wid >> 1) * 32;

    float* sh_bias = (float*)(smem + OFF_BIAS);
    if (tid < BN) sh_bias[tid] = bias[n0 + tid];
    if (tid == 0) *(unsigned*)(smem + OFF_CNT) = 0;

    float acc[4][4][4];
#pragma unroll
    for (int mf = 0; mf < 4; mf++)
#pragma unroll
        for (int nf = 0; nf < 4; nf++)
#pragma unroll
            for (int r = 0; r < 4; r++) acc[mf][nf][r] = 0.f;

    load_tiles(sb, m0, n0, 0, 0, tid);
    load_tiles(sb, m0, n0, 1, 1, tid);

    const int a_row = (lane & 15);
    const int a_chk = (lane >> 4);
    const int b_mat = lane >> 3;
    const int b_sub = (b_mat >> 1) * 8 + (lane & 7);
    const int b_chk = (b_mat & 1);

    int s = 0, s2 = 2;
    for (int kt = 0; kt < DM / BK; ++kt) {
        if (kt == DM / BK - 1) cp_wait0(); else cp_wait1();
        __syncthreads();
        if (kt + 2 < DM / BK) load_tiles(sb, m0, n0, kt + 2, s2, tid);
        const uint32_t abase = sb + OFF_A + s * STG_SZ;
        const uint32_t bbase = sb + OFF_B + s * STG_SZ;
#pragma unroll
        for (int ks = 0; ks < 4; ks++) {
            uint32_t af[4][4], bf[4][2];
#pragma unroll
            for (int mf = 0; mf < 4; mf++) {
                const uint32_t lin = (uint32_t)(wm + mf * 16 + a_row) * 128u
                                   + (uint32_t)(ks * 2 + a_chk) * 16u;
                ldsm_x4(af[mf][0], af[mf][1], af[mf][2], af[mf][3], abase + SWZ(lin));
            }
#pragma unroll
            for (int nfp = 0; nfp < 2; nfp++) {
                const uint32_t lin = (uint32_t)(wn + nfp * 16 + b_sub) * 128u
                                   + (uint32_t)(ks * 2 + b_chk) * 16u;
                ldsm_x4(bf[2 * nfp][0], bf[2 * nfp][1],
                        bf[2 * nfp + 1][0], bf[2 * nfp + 1][1], bbase + SWZ(lin));
            }
#pragma unroll
            for (int mf = 0; mf < 4; mf++)
#pragma unroll
                for (int nf = 0; nf < 4; nf++)
                    mma16816(acc[mf][nf], af[mf], bf[nf]);
        }
        s = (s == 2) ? 0 : s + 1;
        s2 = (s2 == 2) ? 0 : s2 + 1;
    }

    // epilogue: bias add + screen + fused global fine histogram
    float* s_cv = (float*)(smem + OFF_CV);
    int*   s_ci = (int*)(smem + OFF_CI);
    unsigned* s_cnt = (unsigned*)(smem + OFF_CNT);
    unsigned* s_base = (unsigned*)(smem + OFF_BSE);
    __syncthreads();
    const int r0 = lane >> 2, c0 = (lane & 3) * 2;
#pragma unroll
    for (int mf = 0; mf < 4; mf++) {
#pragma unroll
        for (int nf = 0; nf < 4; nf++) {
#pragma unroll
            for (int i = 0; i < 2; i++) {
#pragma unroll
                for (int j = 0; j < 2; j++) {
                    const int gm = m0 + wm + mf * 16 + r0 + i * 8;
                    const int ln = wn + nf * 8 + c0 + j;
                    const float v = acc[mf][nf][i * 2 + j] + sh_bias[ln];
                    const float a = fabsf(v);
                    if (a >= CAND_T) {
                        atomicAdd(&g_fh1[fh_key(a)], 1u);
                        unsigned p = atomicAdd(s_cnt, 1u);
                        if (p < BLK_CAP) { s_cv[p] = v; s_ci[p] = (gm << 14) + n0 + ln; }
                    }
                }
            }
        }
    }
    __syncthreads();
    if (tid == 0) {
        unsigned c = min(*s_cnt, (unsigned)BLK_CAP);
        *s_base = atomicAdd(&g_nwide, c);
        *s_cnt = c;
    }
    __syncthreads();
    const unsigned cnt = *s_cnt, base = *s_base;
    for (unsigned i = tid; i < cnt; i += 256) {
        unsigned p = base + i;
        if (p < WCAP) { g_wide_val[p] = s_cv[i]; g_wide_idx[p] = s_ci[i]; }
    }
}

// --------- bucket: in-block fine scan then filter ----------------------------
__global__ __launch_bounds__(256) void k_bucket() {
    __shared__ unsigned sm[257];
    const unsigned bin = find_kth_fine(g_fh1, K_SEL, sm);
    const float Tbf = __uint_as_float((fh_base() + bin) << 10);
    const float thr = Tbf - MARGIN;
    const unsigned n = min(g_nwide, (unsigned)WCAP);
    const int stride = gridDim.x * blockDim.x;
    for (unsigned i = blockIdx.x * blockDim.x + threadIdx.x; i < n; i += stride) {
        if (fabsf(g_wide_val[i]) >= thr) {
            const int idx = g_wide_idx[i];
            const unsigned g = ((unsigned)idx & (DS - 1)) >> 5;
            unsigned slot = atomicAdd(&g_grp_cnt[g], 1u);
            if (slot < GCAP) g_bk_idx[g * GCAP + slot] = idx;
        }
    }
}

// ------------------------- exact fp32 recompute + fused fine hist ------------
__global__ __launch_bounds__(512)
void k_exact_batch(const float* __restrict__ A, const float* __restrict__ W,
                   const float* __restrict__ bias) {
    extern __shared__ float sw[];   // [32][1025]
    const int g = blockIdx.x, c0 = g * 32;
    const int tid = threadIdx.x;
    const int cl = tid & 31, kr = tid >> 5;
    for (int k = kr; k < DM; k += 16)
        sw[cl * 1025 + k] = W[(size_t)k * DS + c0 + cl];
    __syncthreads();
    const unsigned base = (unsigned)g * GCAP;
    const unsigned cnt = min(g_grp_cnt[g], (unsigned)GCAP);
    const int w = tid >> 5, lane = tid & 31;
    for (unsigned e = w; e < cnt; e += 16) {
        const int idx = g_bk_idx[base + e];
        const int r = idx >> 14, col = idx & (DS - 1);
        const float4* xr = (const float4*)(A + (size_t)r * DM);
        const float* wc = sw + (col - c0) * 1025;
        float s = 0.f;
#pragma unroll
        for (int i = 0; i < 8; i++) {
            const float4 a = xr[lane + 32 * i];
            const int k4 = (lane + 32 * i) * 4;
            s += a.x * wc[k4]; s += a.y * wc[k4 + 1];
            s += a.z * wc[k4 + 2]; s += a.w * wc[k4 + 3];
        }
#pragma unroll
        for (int off = 16; off; off >>= 1) s += __shfl_down_sync(0xffffffffu, s, off);
        if (!lane) {
            const float v = s + bias[col];
            g_exact_val[base + e] = v;
            atomicAdd(&g_fh2[fh_key(fabsf(v))], 1u);
        }
    }
}

// --------- classify: in-block fine scan then classify ------------------------
__global__ __launch_bounds__(256) void k_classify(float* __restrict__ fx) {
    __shared__ unsigned sm[257];
    __shared__ unsigned s_in;
    const unsigned bin = find_kth_fine(g_fh2, K_SEL, sm);
    if (threadIdx.x == 0) s_in = 0;
    __syncthreads();
    const unsigned u = (fh_base() + bin) << 10;
    const float lo = __uint_as_float(u) - NOISE;
    const float hi = __uint_as_float(u + 1024) + NOISE;
    const unsigned n = NGRP * GCAP;
    const int stride = gridDim.x * blockDim.x;
    for (unsigned i = blockIdx.x * blockDim.x + threadIdx.x; i < n; i += stride) {
        const unsigned g = i >> 10, e = i & (GCAP - 1);
        if (e >= min(g_grp_cnt[g], (unsigned)GCAP)) continue;
        const float v = g_exact_val[i];
        const float a = fabsf(v);
        const int idx = g_bk_idx[i];
        if (a >= hi) {
            atomicAdd(&s_in, 1u);
            fx[idx] = v;
            const int row = idx >> 14;
            unsigned slot = atomicAdd(&g_row_cnt[row], 1u);
            if (slot < ROWCAP) {
                g_row_col[row * ROWCAP + slot] = idx & (DS - 1);
                g_row_val[row * ROWCAP + slot] = v;
            }
        } else if (a > lo) {
            unsigned p = atomicAdd(&g_b_cnt, 1u);
            if (p < BCAP) { g_b_idx[p] = idx; g_b_f32[p] = v; }
        }
    }
    __syncthreads();
    if (threadIdx.x == 0 && s_in) atomicAdd(&g_c_in, s_in);
}

__global__ __launch_bounds__(256)
void k_exact64(const float* __restrict__ A, const float* __restrict__ B,
               const float* __restrict__ bias) {
    const int n = min(g_b_cnt, (unsigned)BCAP);
    const int warps = (gridDim.x * blockDim.x) >> 5;
    const int wid = (blockIdx.x * blockDim.x + threadIdx.x) >> 5;
    const int lane = threadIdx.x & 31;
    for (int e = wid; e < n; e += warps) {
        const int idx = g_b_idx[e];
        const int row = idx >> 14, col = idx & (DS - 1);
        const float* xr = A + (size_t)row * DM;
        double s = 0.0;
        for (int m = lane; m < DM; m += 32)
            s += (double)xr[m] * (double)B[(size_t)m * DS + col];
#pragma unroll
        for (int off = 16; off; off >>= 1) s += __shfl_down_sync(0xffffffffu, s, off);
        if (!lane) g_b_v64[e] = fabs(s + (double)bias[col]);
    }
}

// accept: write fx + build accepted list (xhat contribution applied by k_patch)
__global__ __launch_bounds__(1024) void k_accept(float* __restrict__ fx) {
    const int n = min(g_b_cnt, (unsigned)BCAP);
    const unsigned kp = K_SEL - g_c_in;
    for (int i = threadIdx.x; i < n; i += 1024) {
        const double vi = g_b_v64[i];
        const int ii = g_b_idx[i];
        unsigned rank = 0;
        for (int j = 0; j < n; j++) {
            const double vj = g_b_v64[j];
            rank += (vj > vi) || (vj == vi && g_b_idx[j] < ii);
        }
        if (rank < kp) {
            fx[ii] = g_b_f32[i];
            unsigned p = atomicAdd(&g_acc_cnt, 1u);
            if (p < BCAP) { g_acc_idx[p] = ii; g_acc_val[p] = g_b_f32[i]; }
        }
    }
}

// patch: add accepted boundary contributions into xhat (atomic)
__global__ __launch_bounds__(256)
void k_patch(const float* __restrict__ Wd, float* __restrict__ xhat) {
    const int n = (int)min(g_acc_cnt, (unsigned)BCAP);
    const int tid = threadIdx.x;
    for (int e = blockIdx.x; e < n; e += gridDim.x) {
        const int idx = g_acc_idx[e];
        const float v = g_acc_val[e];
        const int row = idx >> 14, col = idx & (DS - 1);
        const float4 w = ((const float4*)(Wd + (size_t)col * DM))[tid];
        float* xr = xhat + (size_t)row * DM + tid * 4;
        atomicAdd(xr + 0, v * w.x);
        atomicAdd(xr + 1, v * w.y);
        atomicAdd(xr + 2, v * w.z);
        atomicAdd(xr + 3, v * w.w);
    }
}

// ------------------------- CSR decode (sure-in only) -------------------------
__global__ __launch_bounds__(256)
void k_decode(const float* __restrict__ Wd, const float* __restrict__ bdec,
              float* __restrict__ xhat) {
    __shared__ int   s_col[ROWCAP];
    __shared__ float s_val[ROWCAP];
    __shared__ int   s_scol[ROWCAP];
    __shared__ float s_sval[ROWCAP];
    const int b = blockIdx.x, tid = threadIdx.x;
    const int cnt = (int)min(g_row_cnt[b], (unsigned)ROWCAP);
    if (tid < cnt) {
        s_col[tid] = g_row_col[b * ROWCAP + tid];
        s_val[tid] = g_row_val[b * ROWCAP + tid];
    }
    __syncthreads();
    if (tid < cnt) {
        const int ci = s_col[tid];
        int rank = 0;
        for (int j = 0; j < cnt; j++) rank += (s_col[j] < ci);
        s_scol[rank] = ci;
        s_sval[rank] = s_val[tid];
    }
    __syncthreads();
    float4 acc = *(const float4*)(bdec + tid * 4);
    int i = 0;
    for (; i + 4 <= cnt; i += 4) {
        const int c0 = s_scol[i], c1 = s_scol[i+1], c2 = s_scol[i+2], c3 = s_scol[i+3];
        const float v0 = s_sval[i], v1 = s_sval[i+1], v2 = s_sval[i+2], v3 = s_sval[i+3];
        const float4 w0 = *(const float4*)(Wd + (size_t)c0 * DM + tid * 4);
        const float4 w1 = *(const float4*)(Wd + (size_t)c1 * DM + tid * 4);
        const float4 w2 = *(const float4*)(Wd + (size_t)c2 * DM + tid * 4);
        const float4 w3 = *(const float4*)(Wd + (size_t)c3 * DM + tid * 4);
        acc.x += v0*w0.x; acc.y += v0*w0.y; acc.z += v0*w0.z; acc.w += v0*w0.w;
        acc.x += v1*w1.x; acc.y += v1*w1.y; acc.z += v1*w1.z; acc.w += v1*w1.w;
        acc.x += v2*w2.x; acc.y += v2*w2.y; acc.z += v2*w2.z; acc.w += v2*w2.w;
        acc.x += v3*w3.x; acc.y += v3*w3.y; acc.z += v3*w3.z; acc.w += v3*w3.w;
    }
    for (; i < cnt; ++i) {
        const int c0 = s_scol[i];
        const float v0 = s_sval[i];
        const float4 w0 = *(const float4*)(Wd + (size_t)c0 * DM + tid * 4);
        acc.x += v0*w0.x; acc.y += v0*w0.y; acc.z += v0*w0.z; acc.w += v0*w0.w;
    }
    *(float4*)(xhat + (size_t)b * DM + tid * 4) = acc;
}

// ------------------------- host launcher -------------------------------------
extern "C" void kernel_launch(void* const* d_in, const int* in_sizes, int n_in,
                              void* d_out, int out_size) {
    const float* x     = (const float*)d_in[0];
    const float* W_enc = (const float*)d_in[1];
    const float* b_enc = (const float*)d_in[2];
    const float* W_dec = (const float*)d_in[3];
    const float* b_dec = (const float*)d_in[4];

    float* out  = (float*)d_out;
    float* xhat = out;

    static float* g_fb_ptr = nullptr;
    static cudaStream_t s2 = nullptr;
    static cudaEvent_t ev_fork = nullptr, ev_w = nullptr, ev_join = nullptr;
    static cudaEvent_t ev_c = nullptr, ev_d = nullptr;
    if (!g_fb_ptr) {
        cudaGetSymbolAddress((void**)&g_fb_ptr, g_fx_fallback);
        cudaStreamCreateWithFlags(&s2, cudaStreamNonBlocking);
        cudaEventCreateWithFlags(&ev_fork, cudaEventDisableTiming);
        cudaEventCreateWithFlags(&ev_w, cudaEventDisableTiming);
        cudaEventCreateWithFlags(&ev_join, cudaEventDisableTiming);
        cudaEventCreateWithFlags(&ev_c, cudaEventDisableTiming);
        cudaEventCreateWithFlags(&ev_d, cudaEventDisableTiming);
    }
    const long long want = (long long)BATCH * DM + (long long)H_TOTAL;
    float* fx = ((long long)out_size >= want) ? (out + (size_t)BATCH * DM) : g_fb_ptr;

    cudaFuncSetAttribute(k_gemm_bf, cudaFuncAttributeMaxDynamicSharedMemorySize, SMEM_GEMM);
    cudaFuncSetAttribute(k_exact_batch, cudaFuncAttributeMaxDynamicSharedMemorySize, 32 * 1025 * 4);

    const int N34 = (DS * 3) / 4;      // main converts cols [0, 12288)
    const int N14 = DS - N34;          // s2 converts cols [12288, 16384)

    // side stream: reset + x-convert + W-convert upper quarter (->ev_w),
    // f_x memset (->ev_join). Main: W-convert lower 3/4 then single GEMM.
    cudaEventRecord(ev_fork, 0);
    cudaStreamWaitEvent(s2, ev_fork, 0);
    k_reset<<<16, 256, 0, s2>>>();
    k_cvt_x<<<1024, 256, 0, s2>>>(x);
    k_cvt_wT<<<dim3(N14 / 32, DM / 32), dim3(32, 8), 0, s2>>>(W_enc, N34);
    cudaEventRecord(ev_w, s2);
    cudaMemsetAsync(fx, 0, (size_t)H_TOTAL * sizeof(float), s2);
    cudaEventRecord(ev_join, s2);

    k_cvt_wT<<<dim3(N34 / 32, DM / 32), dim3(32, 8)>>>(W_enc, 0);
    cudaStreamWaitEvent(0, ev_w, 0);   // covers reset + cvt_x + cvt_wT_hi
    k_gemm_bf<<<dim3(DS / BN, BATCH / BM), 256, SMEM_GEMM>>>(b_enc);

    k_bucket<<<256, 256>>>();
    k_exact_batch<<<NGRP, 512, 32 * 1025 * 4>>>(x, W_enc, b_enc);

    cudaStreamWaitEvent(0, ev_join, 0);
    k_classify<<<256, 256>>>(fx);
    cudaEventRecord(ev_c, 0);

    // decode (sure-in rows) on s2, concurrent with fp64 re-rank on main
    cudaStreamWaitEvent(s2, ev_c, 0);
    k_decode<<<BATCH, 256, 0, s2>>>(W_dec, b_dec, xhat);
    cudaEventRecord(ev_d, s2);

    k_exact64<<<64, 256>>>(x, W_enc, b_enc);
    k_accept<<<1, 1024>>>(fx);
    cudaStreamWaitEvent(0, ev_d, 0);
    k_patch<<<256, 256>>>(W_dec, xhat);
}

// round 17
// speedup vs baseline: 1.0561x; 1.0561x over previous
#include <cuda_runtime.h>
#include <cuda_bf16.h>
#include <cstdint>

#define BATCH   4096
#define DM      1024
#define DS      16384
#define K_SEL   131072
#define H_TOTAL 67108864
#define WCAP    (2*1024*1024)
#define BCAP    8192
#define NOISE   1.5e-4f
#define MARGIN  0.04f
#define CAND_T  4.1f
#define ROWCAP  96
#define BLK_CAP 1024
#define NGRP    512
#define GCAP    1024
#define HWIN    504

// GEMM tiling: 3-stage cp.async pipeline, CTA 128x128, warp 64x32 (proven)
#define BM 128
#define BN 128
#define BK 64
#define STG_SZ   16384
#define OFF_A    0
#define OFF_B    49152
#define OFF_BIAS 98304
#define OFF_CV   98816
#define OFF_CI   102912
#define OFF_CNT  107008
#define OFF_BSE  107012
#define OFF_HIST 107016
#define SMEM_GEMM 107392

#define SWZ(b) ((b) ^ (((b) >> 3) & 0x70))

// ------------------------- device scratch ------------------------------------
__device__ float          g_fx_fallback[H_TOTAL];
__device__ __nv_bfloat16  g_xb[BATCH * DM];
__device__ __nv_bfloat16  g_wbT[DS * DM];        // [n][k] bf16
__device__ float          g_wide_val[WCAP];
__device__ int            g_wide_idx[WCAP];
__device__ unsigned int   g_nwide;
__device__ unsigned int   g_hist1[2048];         // bf coarse (GEMM-fused)
__device__ unsigned int   g_hist2[2048];         // bf refine
__device__ unsigned int   g_hist3[2048];         // exact coarse (exact-fused)
__device__ unsigned int   g_hist4[2048];         // exact refine
__device__ unsigned int   g_grp_cnt[NGRP];
__device__ int            g_bk_idx[NGRP * GCAP];
__device__ float          g_exact_val[NGRP * GCAP];
__device__ unsigned int   g_c_in, g_b_cnt;
__device__ int            g_b_idx[BCAP];
__device__ float          g_b_f32[BCAP];
__device__ double         g_b_v64[BCAP];
__device__ unsigned int   g_acc_cnt;             // accepted boundary list
__device__ int            g_acc_idx[BCAP];
__device__ float          g_acc_val[BCAP];
__device__ unsigned int   g_row_cnt[BATCH];
__device__ int            g_row_col[BATCH * ROWCAP];
__device__ float          g_row_val[BATCH * ROWCAP];

// ------------------------- PTX helpers ---------------------------------------
__device__ __forceinline__ uint32_t smem_u32(const void* p) {
    uint32_t a;
    asm("{ .reg .u64 t; cvta.to.shared.u64 t, %1; cvt.u32.u64 %0, t; }" : "=r"(a) : "l"(p));
    return a;
}
__device__ __forceinline__ void cpasync16(uint32_t dst, const void* src) {
    asm volatile("cp.async.cg.shared.global [%0], [%1], 16;" :: "r"(dst), "l"(src) : "memory");
}
__device__ __forceinline__ void cp_commit() { asm volatile("cp.async.commit_group;" ::: "memory"); }
__device__ __forceinline__ void cp_wait1()  { asm volatile("cp.async.wait_group 1;" ::: "memory"); }
__device__ __forceinline__ void cp_wait0()  { asm volatile("cp.async.wait_group 0;" ::: "memory"); }

__device__ __forceinline__ void ldsm_x4(uint32_t& r0, uint32_t& r1, uint32_t& r2, uint32_t& r3,
                                        uint32_t addr) {
    asm volatile("ldmatrix.sync.aligned.m8n8.x4.shared.b16 {%0,%1,%2,%3}, [%4];"
                 : "=r"(r0), "=r"(r1), "=r"(r2), "=r"(r3) : "r"(addr));
}
__device__ __forceinline__ void mma16816(float* d, const uint32_t* a, const uint32_t* b) {
    asm volatile(
        "mma.sync.aligned.m16n8k16.row.col.f32.bf16.bf16.f32 "
        "{%0,%1,%2,%3}, {%4,%5,%6,%7}, {%8,%9}, {%0,%1,%2,%3};"
        : "+f"(d[0]), "+f"(d[1]), "+f"(d[2]), "+f"(d[3])
        : "r"(a[0]), "r"(a[1]), "r"(a[2]), "r"(a[3]), "r"(b[0]), "r"(b[1]));
}

// ------------------------- in-block k-th selection over a 2048-bin hist -------
struct KthRes { unsigned bin; unsigned rem; };
__device__ __forceinline__ KthRes find_kth_block(const unsigned* __restrict__ hist,
                                                 unsigned K, unsigned* sm /*>=258*/) {
    const int t = threadIdx.x;            // blockDim.x == 256
    unsigned vals[8], s = 0;
#pragma unroll
    for (int j = 0; j < 8; j++) { vals[j] = hist[2047 - (t * 8 + j)]; s += vals[j]; }
    sm[t] = s;
    __syncthreads();
    for (int off = 1; off < 256; off <<= 1) {
        unsigned v = (t >= off) ? sm[t - off] : 0;
        __syncthreads();
        sm[t] += v;
        __syncthreads();
    }
    const unsigned base = t ? sm[t - 1] : 0;
    if (base < K && sm[t] >= K) {
        unsigned cum = base;
#pragma unroll
        for (int j = 0; j < 8; j++) {
            cum += vals[j];
            if (cum >= K) { sm[256] = 2047 - (t * 8 + j); sm[257] = K - (cum - vals[j]); break; }
        }
    }
    __syncthreads();
    KthRes r; r.bin = sm[256]; r.rem = sm[257];
    __syncthreads();
    return r;
}

// ------------------------- reset ---------------------------------------------
__global__ void k_reset() {
    int i = blockIdx.x * blockDim.x + threadIdx.x;
    if (i < 2048) { g_hist1[i] = 0; g_hist2[i] = 0; g_hist3[i] = 0; g_hist4[i] = 0; }
    if (i < NGRP) g_grp_cnt[i] = 0;
    if (i < BATCH) g_row_cnt[i] = 0;
    if (i == 0) { g_nwide = 0; g_c_in = 0; g_b_cnt = 0; g_acc_cnt = 0; }
}

// ------------------------- converts ------------------------------------------
__global__ void k_cvt_x(const float* __restrict__ x) {
    const int n2 = BATCH * DM / 2;
    const int stride = gridDim.x * blockDim.x;
    __nv_bfloat162* o = (__nv_bfloat162*)g_xb;
    const float2* s = (const float2*)x;
    for (int i = blockIdx.x * blockDim.x + threadIdx.x; i < n2; i += stride)
        o[i] = __float22bfloat162_rn(s[i]);
}
// converts W_enc[k][n] -> g_wbT[n][k] for n in [n_lo, n_lo + 32*gridDim.x)
__global__ void k_cvt_wT(const float* __restrict__ W, int n_lo) {
    __shared__ float t[32][33];
    const int n0 = n_lo + blockIdx.x * 32, k0 = blockIdx.y * 32;
    const int tx = threadIdx.x, ty = threadIdx.y;  // 32 x 8
#pragma unroll
    for (int i = 0; i < 4; i++)
        t[ty + 8 * i][tx] = W[(size_t)(k0 + ty + 8 * i) * DS + n0 + tx];
    __syncthreads();
#pragma unroll
    for (int i = 0; i < 4; i++)
        g_wbT[(size_t)(n0 + ty + 8 * i) * DM + k0 + tx] = __float2bfloat16(t[tx][ty + 8 * i]);
}

// ------------------------- bf16 mma.sync GEMM, 3-stage pipeline --------------
__device__ __forceinline__ void load_tiles(uint32_t sb, int m0, int n0, int kt, int s, int tid) {
    const uint32_t ab = sb + OFF_A + s * STG_SZ;
#pragma unroll
    for (int i = 0; i < 4; i++) {
        int c = tid + i * 256;
        int row = c >> 3, chunk = c & 7;
        cpasync16(ab + SWZ((uint32_t)row * 128u + (uint32_t)chunk * 16u),
                  g_xb + (size_t)(m0 + row) * DM + kt * BK + chunk * 8);
    }
    const uint32_t bb = sb + OFF_B + s * STG_SZ;
#pragma unroll
    for (int i = 0; i < 4; i++) {
        int c = tid + i * 256;
        int row = c >> 3, chunk = c & 7;
        cpasync16(bb + SWZ((uint32_t)row * 128u + (uint32_t)chunk * 16u),
                  g_wbT + (size_t)(n0 + row) * DM + kt * BK + chunk * 8);
    }
    cp_commit();
}

__global__ __launch_bounds__(256, 2)
void k_gemm_bf(const float* __restrict__ bias) {
    extern __shared__ char smem[];
    const uint32_t sb = smem_u32(smem);
    const int tid = threadIdx.x, wid = tid >> 5, lane = tid & 31;
    const int m0 = blockIdx.y * BM, n0 = blockIdx.x * BN;
    const int wm = (wid & 1) * 64;
    const int wn = (wid >> 1) * 32;

    float* sh_bias = (float*)(smem + OFF_BIAS);
    unsigned* sh_hist = (unsigned*)(smem + OFF_HIST);
    if (tid < BN) sh_bias[tid] = bias[n0 + tid];
    if (tid == 0) *(unsigned*)(smem + OFF_CNT) = 0;
    if (tid < 64) sh_hist[tid] = 0;

    float acc[4][4][4];
#pragma unroll
    for (int mf = 0; mf < 4; mf++)
#pragma unroll
        for (int nf = 0; nf < 4; nf++)
#pragma unroll
            for (int r = 0; r < 4; r++) acc[mf][nf][r] = 0.f;

    load_tiles(sb, m0, n0, 0, 0, tid);
    load_tiles(sb, m0, n0, 1, 1, tid);

    const int a_row = (lane & 15);
    const int a_chk = (lane >> 4);
    const int b_mat = lane >> 3;
    const int b_sub = (b_mat >> 1) * 8 + (lane & 7);
    const int b_chk = (b_mat & 1);

    int s = 0, s2 = 2;
    for (int kt = 0; kt < DM / BK; ++kt) {
        if (kt == DM / BK - 1) cp_wait0(); else cp_wait1();
        __syncthreads();
        if (kt + 2 < DM / BK) load_tiles(sb, m0, n0, kt + 2, s2, tid);
        const uint32_t abase = sb + OFF_A + s * STG_SZ;
        const uint32_t bbase = sb + OFF_B + s * STG_SZ;
#pragma unroll
        for (int ks = 0; ks < 4; ks++) {
            uint32_t af[4][4], bf[4][2];
#pragma unroll
            for (int mf = 0; mf < 4; mf++) {
                const uint32_t lin = (uint32_t)(wm + mf * 16 + a_row) * 128u
                                   + (uint32_t)(ks * 2 + a_chk) * 16u;
                ldsm_x4(af[mf][0], af[mf][1], af[mf][2], af[mf][3], abase + SWZ(lin));
            }
#pragma unroll
            for (int nfp = 0; nfp < 2; nfp++) {
                const uint32_t lin = (uint32_t)(wn + nfp * 16 + b_sub) * 128u
                                   + (uint32_t)(ks * 2 + b_chk) * 16u;
                ldsm_x4(bf[2 * nfp][0], bf[2 * nfp][1],
                        bf[2 * nfp + 1][0], bf[2 * nfp + 1][1], bbase + SWZ(lin));
            }
#pragma unroll
            for (int mf = 0; mf < 4; mf++)
#pragma unroll
                for (int nf = 0; nf < 4; nf++)
                    mma16816(acc[mf][nf], af[mf], bf[nf]);
        }
        s = (s == 2) ? 0 : s + 1;
        s2 = (s2 == 2) ? 0 : s2 + 1;
    }

    // epilogue: bias add + screen + fused windowed histogram
    float* s_cv = (float*)(smem + OFF_CV);
    int*   s_ci = (int*)(smem + OFF_CI);
    unsigned* s_cnt = (unsigned*)(smem + OFF_CNT);
    unsigned* s_base = (unsigned*)(smem + OFF_BSE);
    __syncthreads();
    const int r0 = lane >> 2, c0 = (lane & 3) * 2;
#pragma unroll
    for (int mf = 0; mf < 4; mf++) {
#pragma unroll
        for (int nf = 0; nf < 4; nf++) {
#pragma unroll
            for (int i = 0; i < 2; i++) {
#pragma unroll
                for (int j = 0; j < 2; j++) {
                    const int gm = m0 + wm + mf * 16 + r0 + i * 8;
                    const int ln = wn + nf * 8 + c0 + j;
                    const float v = acc[mf][nf][i * 2 + j] + sh_bias[ln];
                    const float a = fabsf(v);
                    if (a >= CAND_T) {
                        int b = (int)(__float_as_uint(a) >> 21) - HWIN;
                        b = max(0, min(63, b));
                        atomicAdd(&sh_hist[b], 1u);
                        unsigned p = atomicAdd(s_cnt, 1u);
                        if (p < BLK_CAP) { s_cv[p] = v; s_ci[p] = (gm << 14) + n0 + ln; }
                    }
                }
            }
        }
    }
    __syncthreads();
    if (tid == 0) {
        unsigned c = min(*s_cnt, (unsigned)BLK_CAP);
        *s_base = atomicAdd(&g_nwide, c);
        *s_cnt = c;
    }
    __syncthreads();
    const unsigned cnt = *s_cnt, base = *s_base;
    for (unsigned i = tid; i < cnt; i += 256) {
        unsigned p = base + i;
        if (p < WCAP) { g_wide_val[p] = s_cv[i]; g_wide_idx[p] = s_ci[i]; }
    }
    if (tid < 64 && sh_hist[tid]) atomicAdd(&g_hist1[HWIN + tid], sh_hist[tid]);
}

// --------- bf refine: in-block scan of hist1 then refine into hist2 ----------
__global__ __launch_bounds__(256) void k_histB0() {
    __shared__ unsigned sm[258];
    __shared__ unsigned sh[2048];
    const KthRes k1 = find_kth_block(g_hist1, K_SEL, sm);
    for (int i = threadIdx.x; i < 2048; i += 256) sh[i] = 0;
    __syncthreads();
    const unsigned b1 = k1.bin;
    const unsigned n = min(g_nwide, (unsigned)WCAP);
    const int stride = gridDim.x * blockDim.x;
    for (unsigned i = blockIdx.x * blockDim.x + threadIdx.x; i < n; i += stride) {
        unsigned u = __float_as_uint(fabsf(g_wide_val[i]));
        if ((u >> 21) == b1) atomicAdd(&sh[(u >> 10) & 0x7FF], 1u);
    }
    __syncthreads();
    for (int i = threadIdx.x; i < 2048; i += 256)
        if (sh[i]) atomicAdd(&g_hist2[i], sh[i]);
}

// --------- bucket: in-block scans (hist1, hist2) then filter -----------------
__global__ __launch_bounds__(256) void k_bucket() {
    __shared__ unsigned sm[258];
    const KthRes k1 = find_kth_block(g_hist1, K_SEL, sm);
    const KthRes k2 = find_kth_block(g_hist2, k1.rem, sm);
    const float Tbf = __uint_as_float((k1.bin << 21) | (k2.bin << 10));
    const float thr = Tbf - MARGIN;
    const unsigned n = min(g_nwide, (unsigned)WCAP);
    const int stride = gridDim.x * blockDim.x;
    for (unsigned i = blockIdx.x * blockDim.x + threadIdx.x; i < n; i += stride) {
        if (fabsf(g_wide_val[i]) >= thr) {
            const int idx = g_wide_idx[i];
            const unsigned g = ((unsigned)idx & (DS - 1)) >> 5;
            unsigned slot = atomicAdd(&g_grp_cnt[g], 1u);
            if (slot < GCAP) g_bk_idx[g * GCAP + slot] = idx;
        }
    }
}

// ------------------------- exact fp32 recompute + fused hist -----------------
__global__ __launch_bounds__(1024)
void k_exact_batch(const float* __restrict__ A, const float* __restrict__ W,
                   const float* __restrict__ bias) {
    extern __shared__ float sw[];   // [32][1025]
    __shared__ unsigned sh_h[64];
    const int g = blockIdx.x, c0 = g * 32;
    const int tid = threadIdx.x;
    const int cl = tid & 31, kr = tid >> 5;   // 32 k-rows
    if (tid < 64) sh_h[tid] = 0;
    for (int k = kr; k < DM; k += 32)
        sw[cl * 1025 + k] = W[(size_t)k * DS + c0 + cl];
    __syncthreads();
    const unsigned base = (unsigned)g * GCAP;
    const unsigned cnt = min(g_grp_cnt[g], (unsigned)GCAP);
    const int w = tid >> 5, lane = tid & 31;
    for (unsigned e = w; e < cnt; e += 32) {
        const int idx = g_bk_idx[base + e];
        const int r = idx >> 14, col = idx & (DS - 1);
        const float4* xr = (const float4*)(A + (size_t)r * DM);
        const float* wc = sw + (col - c0) * 1025;
        float s = 0.f;
#pragma unroll
        for (int i = 0; i < 8; i++) {
            const float4 a = xr[lane + 32 * i];
            const int k4 = (lane + 32 * i) * 4;
            s += a.x * wc[k4]; s += a.y * wc[k4 + 1];
            s += a.z * wc[k4 + 2]; s += a.w * wc[k4 + 3];
        }
#pragma unroll
        for (int off = 16; off; off >>= 1) s += __shfl_down_sync(0xffffffffu, s, off);
        if (!lane) {
            const float v = s + bias[col];
            g_exact_val[base + e] = v;
            int b = (int)(__float_as_uint(fabsf(v)) >> 21) - HWIN;
            b = max(0, min(63, b));
            atomicAdd(&sh_h[b], 1u);
        }
    }
    __syncthreads();
    if (tid < 64 && sh_h[tid]) atomicAdd(&g_hist3[HWIN + tid], sh_h[tid]);
}

// --------- exact refine: in-block scan of hist3 then refine into hist4 -------
__global__ __launch_bounds__(256) void k_histB1() {
    __shared__ unsigned sm[258];
    __shared__ unsigned sh[2048];
    const KthRes k1 = find_kth_block(g_hist3, K_SEL, sm);
    for (int i = threadIdx.x; i < 2048; i += 256) sh[i] = 0;
    __syncthreads();
    const unsigned b1 = k1.bin;
    const unsigned n = NGRP * GCAP;
    const int stride = gridDim.x * blockDim.x;
    for (unsigned i = blockIdx.x * blockDim.x + threadIdx.x; i < n; i += stride) {
        const unsigned g = i >> 10, e = i & (GCAP - 1);
        if (e < min(g_grp_cnt[g], (unsigned)GCAP)) {
            unsigned u = __float_as_uint(fabsf(g_exact_val[i]));
            if ((u >> 21) == b1) atomicAdd(&sh[(u >> 10) & 0x7FF], 1u);
        }
    }
    __syncthreads();
    for (int i = threadIdx.x; i < 2048; i += 256)
        if (sh[i]) atomicAdd(&g_hist4[i], sh[i]);
}

// --------- classify: in-block scans (hist3, hist4) then classify -------------
__global__ __launch_bounds__(256) void k_classify(float* __restrict__ fx) {
    __shared__ unsigned sm[258];
    __shared__ unsigned s_in;
    const KthRes k1 = find_kth_block(g_hist3, K_SEL, sm);
    const KthRes k2 = find_kth_block(g_hist4, k1.rem, sm);
    if (threadIdx.x == 0) s_in = 0;
    __syncthreads();
    const unsigned u = (k1.bin << 21) | (k2.bin << 10);
    const float lo = __uint_as_float(u) - NOISE;
    const float hi = __uint_as_float(u + 1024) + NOISE;
    const unsigned n = NGRP * GCAP;
    const int stride = gridDim.x * blockDim.x;
    for (unsigned i = blockIdx.x * blockDim.x + threadIdx.x; i < n; i += stride) {
        const unsigned g = i >> 10, e = i & (GCAP - 1);
        if (e >= min(g_grp_cnt[g], (unsigned)GCAP)) continue;
        const float v = g_exact_val[i];
        const float a = fabsf(v);
        const int idx = g_bk_idx[i];
        if (a >= hi) {
            atomicAdd(&s_in, 1u);
            fx[idx] = v;
            const int row = idx >> 14;
            unsigned slot = atomicAdd(&g_row_cnt[row], 1u);
            if (slot < ROWCAP) {
                g_row_col[row * ROWCAP + slot] = idx & (DS - 1);
                g_row_val[row * ROWCAP + slot] = v;
            }
        } else if (a > lo) {
            unsigned p = atomicAdd(&g_b_cnt, 1u);
            if (p < BCAP) { g_b_idx[p] = idx; g_b_f32[p] = v; }
        }
    }
    __syncthreads();
    if (threadIdx.x == 0 && s_in) atomicAdd(&g_c_in, s_in);
}

__global__ __launch_bounds__(256)
void k_exact64(const float* __restrict__ A, const float* __restrict__ B,
               const float* __restrict__ bias) {
    const int n = min(g_b_cnt, (unsigned)BCAP);
    const int warps = (gridDim.x * blockDim.x) >> 5;
    const int wid = (blockIdx.x * blockDim.x + threadIdx.x) >> 5;
    const int lane = threadIdx.x & 31;
    for (int e = wid; e < n; e += warps) {
        const int idx = g_b_idx[e];
        const int row = idx >> 14, col = idx & (DS - 1);
        const float* xr = A + (size_t)row * DM;
        double s = 0.0;
        for (int m = lane; m < DM; m += 32)
            s += (double)xr[m] * (double)B[(size_t)m * DS + col];
#pragma unroll
        for (int off = 16; off; off >>= 1) s += __shfl_down_sync(0xffffffffu, s, off);
        if (!lane) g_b_v64[e] = fabs(s + (double)bias[col]);
    }
}

// accept: write fx + build accepted list (xhat contribution applied by k_patch)
__global__ __launch_bounds__(1024) void k_accept(float* __restrict__ fx) {
    const int n = min(g_b_cnt, (unsigned)BCAP);
    const unsigned kp = K_SEL - g_c_in;
    for (int i = threadIdx.x; i < n; i += 1024) {
        const double vi = g_b_v64[i];
        const int ii = g_b_idx[i];
        unsigned rank = 0;
        for (int j = 0; j < n; j++) {
            const double vj = g_b_v64[j];
            rank += (vj > vi) || (vj == vi && g_b_idx[j] < ii);
        }
        if (rank < kp) {
            fx[ii] = g_b_f32[i];
            unsigned p = atomicAdd(&g_acc_cnt, 1u);
            if (p < BCAP) { g_acc_idx[p] = ii; g_acc_val[p] = g_b_f32[i]; }
        }
    }
}

// patch: add accepted boundary contributions into xhat (atomic)
__global__ __launch_bounds__(256)
void k_patch(const float* __restrict__ Wd, float* __restrict__ xhat) {
    const int n = (int)min(g_acc_cnt, (unsigned)BCAP);
    const int tid = threadIdx.x;
    for (int e = blockIdx.x; e < n; e += gridDim.x) {
        const int idx = g_acc_idx[e];
        const float v = g_acc_val[e];
        const int row = idx >> 14, col = idx & (DS - 1);
        const float4 w = ((const float4*)(Wd + (size_t)col * DM))[tid];
        float* xr = xhat + (size_t)row * DM + tid * 4;
        atomicAdd(xr + 0, v * w.x);
        atomicAdd(xr + 1, v * w.y);
        atomicAdd(xr + 2, v * w.z);
        atomicAdd(xr + 3, v * w.w);
    }
}

// ------------------------- CSR decode (sure-in only) -------------------------
__global__ __launch_bounds__(256)
void k_decode(const float* __restrict__ Wd, const float* __restrict__ bdec,
              float* __restrict__ xhat) {
    __shared__ int   s_col[ROWCAP];
    __shared__ float s_val[ROWCAP];
    __shared__ int   s_scol[ROWCAP];
    __shared__ float s_sval[ROWCAP];
    const int b = blockIdx.x, tid = threadIdx.x;
    const int cnt = (int)min(g_row_cnt[b], (unsigned)ROWCAP);
    if (tid < cnt) {
        s_col[tid] = g_row_col[b * ROWCAP + tid];
        s_val[tid] = g_row_val[b * ROWCAP + tid];
    }
    __syncthreads();
    if (tid < cnt) {
        const int ci = s_col[tid];
        int rank = 0;
        for (int j = 0; j < cnt; j++) rank += (s_col[j] < ci);
        s_scol[rank] = ci;
        s_sval[rank] = s_val[tid];
    }
    __syncthreads();
    float4 acc = *(const float4*)(bdec + tid * 4);
    int i = 0;
    for (; i + 4 <= cnt; i += 4) {
        const int c0 = s_scol[i], c1 = s_scol[i+1], c2 = s_scol[i+2], c3 = s_scol[i+3];
        const float v0 = s_sval[i], v1 = s_sval[i+1], v2 = s_sval[i+2], v3 = s_sval[i+3];
        const float4 w0 = *(const float4*)(Wd + (size_t)c0 * DM + tid * 4);
        const float4 w1 = *(const float4*)(Wd + (size_t)c1 * DM + tid * 4);
        const float4 w2 = *(const float4*)(Wd + (size_t)c2 * DM + tid * 4);
        const float4 w3 = *(const float4*)(Wd + (size_t)c3 * DM + tid * 4);
        acc.x += v0*w0.x; acc.y += v0*w0.y; acc.z += v0*w0.z; acc.w += v0*w0.w;
        acc.x += v1*w1.x; acc.y += v1*w1.y; acc.z += v1*w1.z; acc.w += v1*w1.w;
        acc.x += v2*w2.x; acc.y += v2*w2.y; acc.z += v2*w2.z; acc.w += v2*w2.w;
        acc.x += v3*w3.x; acc.y += v3*w3.y; acc.z += v3*w3.z; acc.w += v3*w3.w;
    }
    for (; i < cnt; ++i) {
        const int c0 = s_scol[i];
        const float v0 = s_sval[i];
        const float4 w0 = *(const float4*)(Wd + (size_t)c0 * DM + tid * 4);
        acc.x += v0*w0.x; acc.y += v0*w0.y; acc.z += v0*w0.z; acc.w += v0*w0.w;
    }
    *(float4*)(xhat + (size_t)b * DM + tid * 4) = acc;
}

// ------------------------- host launcher -------------------------------------
extern "C" void kernel_launch(void* const* d_in, const int* in_sizes, int n_in,
                              void* d_out, int out_size) {
    const float* x     = (const float*)d_in[0];
    const float* W_enc = (const float*)d_in[1];
    const float* b_enc = (const float*)d_in[2];
    const float* W_dec = (const float*)d_in[3];
    const float* b_dec = (const float*)d_in[4];

    float* out  = (float*)d_out;
    float* xhat = out;

    static float* g_fb_ptr = nullptr;
    static cudaStream_t s2 = nullptr;
    static cudaEvent_t ev_fork = nullptr, ev_w = nullptr, ev_join = nullptr;
    static cudaEvent_t ev_c = nullptr, ev_d = nullptr;
    if (!g_fb_ptr) {
        cudaGetSymbolAddress((void**)&g_fb_ptr, g_fx_fallback);
        cudaStreamCreateWithFlags(&s2, cudaStreamNonBlocking);
        cudaEventCreateWithFlags(&ev_fork, cudaEventDisableTiming);
        cudaEventCreateWithFlags(&ev_w, cudaEventDisableTiming);
        cudaEventCreateWithFlags(&ev_join, cudaEventDisableTiming);
        cudaEventCreateWithFlags(&ev_c, cudaEventDisableTiming);
        cudaEventCreateWithFlags(&ev_d, cudaEventDisableTiming);
    }
    const long long want = (long long)BATCH * DM + (long long)H_TOTAL;
    float* fx = ((long long)out_size >= want) ? (out + (size_t)BATCH * DM) : g_fb_ptr;

    cudaFuncSetAttribute(k_gemm_bf, cudaFuncAttributeMaxDynamicSharedMemorySize, SMEM_GEMM);
    cudaFuncSetAttribute(k_exact_batch, cudaFuncAttributeMaxDynamicSharedMemorySize, 32 * 1025 * 4);

    const int N34 = (DS * 3) / 4;      // main converts cols [0, 12288)
    const int N14 = DS - N34;          // s2 converts cols [12288, 16384)

    // side stream: reset + x-convert + W-convert upper quarter (->ev_w),
    // f_x memset (->ev_join). Main: W-convert lower 3/4 then single GEMM.
    cudaEventRecord(ev_fork, 0);
    cudaStreamWaitEvent(s2, ev_fork, 0);
    k_reset<<<16, 256, 0, s2>>>();
    k_cvt_x<<<1024, 256, 0, s2>>>(x);
    k_cvt_wT<<<dim3(N14 / 32, DM / 32), dim3(32, 8), 0, s2>>>(W_enc, N34);
    cudaEventRecord(ev_w, s2);
    cudaMemsetAsync(fx, 0, (size_t)H_TOTAL * sizeof(float), s2);
    cudaEventRecord(ev_join, s2);

    k_cvt_wT<<<dim3(N34 / 32, DM / 32), dim3(32, 8)>>>(W_enc, 0);
    cudaStreamWaitEvent(0, ev_w, 0);   // covers reset + cvt_x + cvt_wT_hi
    k_gemm_bf<<<dim3(DS / BN, BATCH / BM), 256, SMEM_GEMM>>>(b_enc);

    k_histB0<<<256, 256>>>();
    k_bucket<<<256, 256>>>();
    k_exact_batch<<<NGRP, 1024, 32 * 1025 * 4>>>(x, W_enc, b_enc);
    k_histB1<<<512, 256>>>();

    cudaStreamWaitEvent(0, ev_join, 0);
    k_classify<<<256, 256>>>(fx);
    cudaEventRecord(ev_c, 0);

    // decode (sure-in rows) on s2, concurrent with fp64 re-rank on main
    cudaStreamWaitEvent(s2, ev_c, 0);
    k_decode<<<BATCH, 256, 0, s2>>>(W_dec, b_dec, xhat);
    cudaEventRecord(ev_d, s2);

    k_exact64<<<64, 256>>>(x, W_enc, b_enc);
    k_accept<<<1, 1024>>>(fx);
    cudaStreamWaitEvent(0, ev_d, 0);
    k_patch<<<256, 256>>>(W_dec, xhat);
}